// round 1
// baseline (speedup 1.0000x reference)
#include <cuda_runtime.h>
#include <cuda_bf16.h>
#include <math_constants.h>

// Problem: B=256, N=256, K=16, DIM=128
//   gated[b,n,k,:] = extra[b,n,:] * neighbor[b,n,k,:]
//   z = gated @ w1[:128] + weight[...,None]*w1[128]       [16,128] per (b,n)
//   z = leaky_relu(z, 0.2)
//   a[k] = z @ w2                                          [16]
//   a = softmax(a)  (over K)
//   out[b,n,:] = sum_k a[k] * neighbor[b,n,k,:]
//
// Inputs (metadata order):
//  0: self_vectors  [B,N,128]  f32   (UNUSED)
//  1: neighbor      [B,N,16,128] f32
//  2: batch_size    (scalar)         (UNUSED)
//  3: masks         [B,N] i32        (UNUSED)
//  4: neighbor_weight [B,N,16] f32
//  5: extra         [B,N,128] f32
//  6: w_1           [129,128] f32
//  7: w_2           [128,1]  f32
// out: [B,N,128] f32

#define DIMX    128
#define KN      16
#define GROUP   16
#define NTHREADS 256

// shared layout (floats):
//  w1s   : 129*128 = 16512   (rows 0..127 = W, row 128 = bias row)
//  w2s   : 128
//  nb    : 16*128  = 2048    (raw neighbor tile)
//  gt    : 16*128  = 2048    (gated tile)
//  exs   : 128
//  wts   : 16
//  sal   : 16
#define SM_W1   0
#define SM_W2   (129*128)
#define SM_NB   (SM_W2 + 128)
#define SM_GT   (SM_NB + KN*DIMX)
#define SM_EX   (SM_GT + KN*DIMX)
#define SM_WT   (SM_EX + DIMX)
#define SM_AL   (SM_WT + KN)
#define SM_FLOATS (SM_AL + KN)

__device__ __forceinline__ float leaky02(float v) {
    return v > 0.0f ? v : 0.2f * v;
}

extern "C" __global__ void __launch_bounds__(NTHREADS)
agg_kernel(const float* __restrict__ neighbor,
           const float* __restrict__ nweight,
           const float* __restrict__ extra,
           const float* __restrict__ w1,
           const float* __restrict__ w2,
           float* __restrict__ out,
           int total_bn)
{
    extern __shared__ float sm[];
    float* w1s = sm + SM_W1;
    float* w2s = sm + SM_W2;
    float* nb  = sm + SM_NB;
    float* gt  = sm + SM_GT;
    float* exs = sm + SM_EX;
    float* wts = sm + SM_WT;
    float* sal = sm + SM_AL;

    const int tid  = threadIdx.x;
    const int warp = tid >> 5;
    const int lane = tid & 31;

    // ---- load weights once per block ----
    {
        const float4* src = (const float4*)w1;
        float4* dst = (float4*)w1s;
        for (int i = tid; i < (129 * DIMX) / 4; i += NTHREADS) dst[i] = src[i];
        if (tid < DIMX / 4) ((float4*)w2s)[tid] = ((const float4*)w2)[tid];
    }
    __syncthreads();

    const int bn0 = blockIdx.x * GROUP;

    for (int g = 0; g < GROUP; ++g) {
        const int bn = bn0 + g;
        if (bn >= total_bn) break;

        // ---- load per-(b,n) tiles ----
        {
            const float4* nsrc = (const float4*)(neighbor + (size_t)bn * KN * DIMX);
            float4* ndst = (float4*)nb;
            #pragma unroll
            for (int i = tid; i < (KN * DIMX) / 4; i += NTHREADS) ndst[i] = nsrc[i];
            if (tid < DIMX / 4)
                ((float4*)exs)[tid] = ((const float4*)(extra + (size_t)bn * DIMX))[tid];
            if (tid < KN)
                wts[tid] = nweight[(size_t)bn * KN + tid];
        }
        __syncthreads();

        // ---- gated tile ----
        #pragma unroll
        for (int i = tid; i < KN * DIMX; i += NTHREADS)
            gt[i] = nb[i] * exs[i & (DIMX - 1)];
        __syncthreads();

        // ---- z = gated @ W + bias ; leaky ; dot w2 ----
        // warp w handles k0=2w, k1=2w+1 ; lane handles e = 4*lane .. 4*lane+3
        const int k0 = warp * 2;
        const int k1 = k0 + 1;
        const float* g0p = gt + k0 * DIMX;
        const float* g1p = gt + k1 * DIMX;

        float4 z0 = make_float4(0.f, 0.f, 0.f, 0.f);
        float4 z1 = make_float4(0.f, 0.f, 0.f, 0.f);

        #pragma unroll 8
        for (int d = 0; d < DIMX; ++d) {
            const float4 w = ((const float4*)(w1s + d * DIMX))[lane];
            const float a0 = g0p[d];
            const float a1 = g1p[d];
            z0.x = fmaf(a0, w.x, z0.x);
            z0.y = fmaf(a0, w.y, z0.y);
            z0.z = fmaf(a0, w.z, z0.z);
            z0.w = fmaf(a0, w.w, z0.w);
            z1.x = fmaf(a1, w.x, z1.x);
            z1.y = fmaf(a1, w.y, z1.y);
            z1.z = fmaf(a1, w.z, z1.z);
            z1.w = fmaf(a1, w.w, z1.w);
        }

        // bias row (w1[128]) scaled by neighbor_weight
        {
            const float4 b = ((const float4*)(w1s + 128 * DIMX))[lane];
            const float wk0 = wts[k0];
            const float wk1 = wts[k1];
            z0.x = fmaf(wk0, b.x, z0.x);
            z0.y = fmaf(wk0, b.y, z0.y);
            z0.z = fmaf(wk0, b.z, z0.z);
            z0.w = fmaf(wk0, b.w, z0.w);
            z1.x = fmaf(wk1, b.x, z1.x);
            z1.y = fmaf(wk1, b.y, z1.y);
            z1.z = fmaf(wk1, b.z, z1.z);
            z1.w = fmaf(wk1, b.w, z1.w);
        }

        // leaky relu + dot with w2 (partial over this lane's 4 e's)
        float p0, p1;
        {
            const float4 v2 = ((const float4*)w2s)[lane];
            p0 = leaky02(z0.x) * v2.x + leaky02(z0.y) * v2.y +
                 leaky02(z0.z) * v2.z + leaky02(z0.w) * v2.w;
            p1 = leaky02(z1.x) * v2.x + leaky02(z1.y) * v2.y +
                 leaky02(z1.z) * v2.z + leaky02(z1.w) * v2.w;
        }

        // warp reduce over 32 lanes
        #pragma unroll
        for (int off = 16; off > 0; off >>= 1) {
            p0 += __shfl_xor_sync(0xffffffffu, p0, off);
            p1 += __shfl_xor_sync(0xffffffffu, p1, off);
        }
        if (lane == 0) { sal[k0] = p0; sal[k1] = p1; }
        __syncthreads();

        // ---- softmax over K=16 (warp 0) ----
        if (warp == 0) {
            float v = (lane < KN) ? sal[lane] : -CUDART_INF_F;
            float m = v;
            #pragma unroll
            for (int off = 16; off > 0; off >>= 1)
                m = fmaxf(m, __shfl_xor_sync(0xffffffffu, m, off));
            float ev = (lane < KN) ? __expf(v - m) : 0.f;
            float s = ev;
            #pragma unroll
            for (int off = 16; off > 0; off >>= 1)
                s += __shfl_xor_sync(0xffffffffu, s, off);
            if (lane < KN) sal[lane] = ev / s;
        }
        __syncthreads();

        // ---- output: out[d] = sum_k alpha[k] * nb[k][d] ----
        if (tid < DIMX) {
            float acc = 0.f;
            #pragma unroll
            for (int k = 0; k < KN; ++k)
                acc = fmaf(sal[k], nb[k * DIMX + tid], acc);
            out[(size_t)bn * DIMX + tid] = acc;
        }
        __syncthreads();
    }
}

extern "C" void kernel_launch(void* const* d_in, const int* in_sizes, int n_in,
                              void* d_out, int out_size) {
    const float* neighbor = (const float*)d_in[1];
    const float* nweight  = (const float*)d_in[4];
    const float* extra    = (const float*)d_in[5];
    const float* w1       = (const float*)d_in[6];
    const float* w2       = (const float*)d_in[7];
    float* out            = (float*)d_out;

    const int total_bn = in_sizes[5] / DIMX;   // extra_vector element count / DIM
    const int nblocks  = (total_bn + GROUP - 1) / GROUP;
    const size_t smem_bytes = (size_t)SM_FLOATS * sizeof(float);

    static bool attr_set = false;
    // idempotent, cheap; safe to call every launch (not a stream op)
    cudaFuncSetAttribute(agg_kernel, cudaFuncAttributeMaxDynamicSharedMemorySize,
                         (int)smem_bytes);
    (void)attr_set;

    agg_kernel<<<nblocks, NTHREADS, smem_bytes>>>(neighbor, nweight, extra,
                                                  w1, w2, out, total_bn);
}